// round 14
// baseline (speedup 1.0000x reference)
#include <cuda_runtime.h>

// preds: [16,8,17,128,128] f32  -> flattened N=128, K=17, H=W=128
// gt:    [16,8,10,17,2]   f32  -> N=128, P=10, K=17, (x,y)
// out:   2 floats: total_within, total_across
//
// 128 blocks x 32 threads, one n per block. Each person is split across TWO
// lanes (lanes 0..19: person = lane%10, half = lane/10, 8-9 keypoints each)
// to halve per-lane load chains; half-moments merge with one shuffle.
// Cross-block protocol: single packed u64 atomicAdd
//   bits[56:64) count | bits[26:56) within_q16 | bits[0:26) across_q18
// The block seeing prev count == 127 writes out from registers.

#define N_FLAT 128
#define P_NUM 10
#define K_NUM 17
#define HW 128

#define Q_WITHIN 65536.0f    // 2^16
#define Q_ACROSS 262144.0f   // 2^18
#define SH_WITHIN 26
#define SH_COUNT 56

__device__ unsigned long long g_acc = 0ull;

__global__ __launch_bounds__(32) void group_loss_fused(
    const float* __restrict__ preds,
    const float* __restrict__ gt,
    float* __restrict__ out)
{
    const int n = blockIdx.x;
    const int lane = threadIdx.x;
    const int pr   = (lane < 20) ? (lane % P_NUM) : 0;   // person
    const int half = lane / P_NUM;                       // 0 or 1 (active <20)
    const bool active = (lane < 20);

    // half 0: k = 0..8 (9 kps), half 1: k = 9..16 (8 kps)
    const int k0 = (half == 0) ? 0 : 9;
    const int nk = (half == 0) ? 9 : 8;

    float sum = 0.0f, sumsq = 0.0f, cnt = 0.0f;
    if (active) {
        const float2* gp = ((const float2*)gt) + (n * P_NUM + pr) * K_NUM + k0;
        const float* pp = preds + n * (K_NUM * HW * HW);

        float2 g[9];
        #pragma unroll
        for (int k = 0; k < 9; k++)
            if (k < nk) g[k] = gp[k];          // up to 9 indep LDG.64

        #pragma unroll
        for (int k = 0; k < 9; k++) {
            if (k >= nk) break;
            // jnp.round = round half to even; rintf matches (RN mode)
            const int x = (int)rintf(g[k].x * 0.25f);
            const int y = (int)rintf(g[k].y * 0.25f);
            const bool valid = (x >= 0) & (x < HW) & (y >= 0) & (y < HW);
            const int xc = min(max(x, 0), HW - 1);
            const int yc = min(max(y, 0), HW - 1);
            float v = pp[((k0 + k) * HW + yc) * HW + xc];
            v = valid ? v : 0.0f;
            sum   += v;
            sumsq += v * v;
            cnt   += valid ? 1.0f : 0.0f;
        }
    }

    // merge half 1 (lanes 10..19) into half 0 (lanes 0..9)
    sum   += __shfl_sync(0xffffffffu, sum,   lane + P_NUM);
    sumsq += __shfl_sync(0xffffffffu, sumsq, lane + P_NUM);
    cnt   += __shfl_sync(0xffffffffu, cnt,   lane + P_NUM);

    const bool owner = (lane < P_NUM);
    const float safe = fmaxf(cnt, 1.0f);
    const float e = sum / safe;
    // E[(v-e)^2] = E[v^2] - e^2 over valid kps
    float within_p = (owner && cnt > 0.0f) ? fmaxf(sumsq / safe - e * e, 0.0f) : 0.0f;

    const bool pvalid = owner && (cnt > 0.0f);
    const unsigned vmask = __ballot_sync(0xffffffffu, pvalid);
    const int nv = __popc(vmask & 0x3ffu);

    // invalid persons get distinct huge sentinel embeds: any pair with one
    // has |ej - ei| >> 1 -> hinge term exactly 0.
    const float ebc = pvalid ? e : 1.0e7f * (float)(lane + 2);

    float ej[P_NUM];
    #pragma unroll
    for (int j = 0; j < P_NUM; j++)
        ej[j] = __shfl_sync(0xffffffffu, ebc, j);

    float hinge_row = 0.0f;
    if (pvalid) {
        #pragma unroll
        for (int j = 0; j < P_NUM; j++) {
            if (j == lane) continue;
            hinge_row += fmaxf(1.0f - fabsf(ej[j] - e), 0.0f);
        }
    }

    // butterfly reduce two scalars (lanes >= 10 carry zeros)
    #pragma unroll
    for (int off = 16; off > 0; off >>= 1) {
        within_p  += __shfl_xor_sync(0xffffffffu, within_p,  off);
        hinge_row += __shfl_xor_sync(0xffffffffu, hinge_row, off);
    }

    if (lane == 0) {
        const float within = within_p * (1.0f / (float)P_NUM);   // >= 0, O(1)
        const float denom = (float)(nv * (nv - 1));
        const float across = (denom > 0.0f) ? hinge_row / denom : 0.0f; // [0,1]

        const unsigned long long wq = (unsigned long long)__float2uint_rn(within * Q_WITHIN);
        const unsigned long long aq = (unsigned long long)__float2uint_rn(across * Q_ACROSS);
        const unsigned long long contrib =
            (1ull << SH_COUNT) | (wq << SH_WITHIN) | aq;

        const unsigned long long prev = atomicAdd(&g_acc, contrib);

        if ((prev >> SH_COUNT) == (unsigned long long)(N_FLAT - 1)) {
            const unsigned long long tot = prev + contrib;
            const unsigned long long wsum = (tot >> SH_WITHIN) & ((1ull << (SH_COUNT - SH_WITHIN)) - 1ull);
            const unsigned long long asum = tot & ((1ull << SH_WITHIN) - 1ull);
            out[0] = (float)((double)wsum * (1.0 / ((double)Q_WITHIN * N_FLAT)));
            out[1] = (float)((double)asum * (1.0 / ((double)Q_ACROSS * N_FLAT)));
            g_acc = 0ull;   // reset for next graph replay
        }
    }
}

extern "C" void kernel_launch(void* const* d_in, const int* in_sizes, int n_in,
                              void* d_out, int out_size)
{
    const float* preds = (const float*)d_in[0];
    const float* gt    = (const float*)d_in[1];
    float* out = (float*)d_out;
    group_loss_fused<<<N_FLAT, 32>>>(preds, gt, out);
}

// round 15
// speedup vs baseline: 1.0097x; 1.0097x over previous
#include <cuda_runtime.h>

// preds: [16,8,17,128,128] f32  -> flattened N=128, K=17, H=W=128
// gt:    [16,8,10,17,2]   f32  -> N=128, P=10, K=17, (x,y)
// out:   2 floats: total_within, total_across
//
// FINAL (locked): 128 blocks x 32 threads, one n per block, lane p (<10)
// owns person p end-to-end in registers. No smem, no __syncthreads.
// Cross-block protocol is a single packed u64 atomicAdd:
//   bits [56:64) block-completion count
//   bits [26:56) sum of within_n, q16  (< 2^30, no carry)
//   bits [ 0:26) sum of across_n, q18  (< 2^26, no carry)
// The block whose returned prev count == 127 writes out from registers and
// resets the accumulator for the next graph replay. Integer adds are
// order-invariant -> bit-deterministic across replays.

#define N_FLAT 128
#define P_NUM 10
#define K_NUM 17
#define HW 128

#define Q_WITHIN 65536.0f    // 2^16
#define Q_ACROSS 262144.0f   // 2^18
#define SH_WITHIN 26
#define SH_COUNT 56

__device__ unsigned long long g_acc = 0ull;

__global__ __launch_bounds__(32) void group_loss_fused(
    const float* __restrict__ preds,
    const float* __restrict__ gt,
    float* __restrict__ out)
{
    const int n = blockIdx.x;
    const int lane = threadIdx.x;

    // per-person one-pass moments (lanes >= P_NUM carry zeros)
    float sum = 0.0f, sumsq = 0.0f, cnt = 0.0f;
    if (lane < P_NUM) {
        const float2* gp = ((const float2*)gt) + (n * P_NUM + lane) * K_NUM;
        const float* pp = preds + n * (K_NUM * HW * HW);

        // stage coords first: 17 independent LDG.64, full MLP
        float2 g[K_NUM];
        #pragma unroll
        for (int k = 0; k < K_NUM; k++) g[k] = gp[k];

        #pragma unroll
        for (int k = 0; k < K_NUM; k++) {
            // jnp.round = round half to even; rintf matches (RN mode)
            const int x = (int)rintf(g[k].x * 0.25f);
            const int y = (int)rintf(g[k].y * 0.25f);
            const bool valid = (x >= 0) & (x < HW) & (y >= 0) & (y < HW);
            const int xc = min(max(x, 0), HW - 1);
            const int yc = min(max(y, 0), HW - 1);
            float v = pp[(k * HW + yc) * HW + xc];
            v = valid ? v : 0.0f;
            sum   += v;
            sumsq += v * v;
            cnt   += valid ? 1.0f : 0.0f;
        }
    }
    const float safe = fmaxf(cnt, 1.0f);
    const float e = sum / safe;
    // E[(v-e)^2] = E[v^2] - e^2 over valid kps
    float within_p = (cnt > 0.0f) ? fmaxf(sumsq / safe - e * e, 0.0f) : 0.0f;

    const bool pvalid = (lane < P_NUM) && (cnt > 0.0f);
    const unsigned vmask = __ballot_sync(0xffffffffu, pvalid);
    const int nv = __popc(vmask);

    // invalid persons get distinct huge sentinel embeds: any pair with one
    // has |ej - ei| >> 1 -> its hinge term is exactly 0.
    const float ebc = pvalid ? e : 1.0e7f * (float)(lane + 2);

    float ej[P_NUM];
    #pragma unroll
    for (int j = 0; j < P_NUM; j++)
        ej[j] = __shfl_sync(0xffffffffu, ebc, j);

    float hinge_row = 0.0f;
    if (pvalid) {
        #pragma unroll
        for (int j = 0; j < P_NUM; j++) {
            if (j == lane) continue;
            hinge_row += fmaxf(1.0f - fabsf(ej[j] - e), 0.0f);
        }
    }

    // 4-level butterfly: partials are nonzero only in lanes 0..9, so a
    // 16-lane butterfly (offs 8,4,2,1) fully reduces them into lane 0.
    #pragma unroll
    for (int off = 8; off > 0; off >>= 1) {
        within_p  += __shfl_xor_sync(0xffffffffu, within_p,  off);
        hinge_row += __shfl_xor_sync(0xffffffffu, hinge_row, off);
    }

    if (lane == 0) {
        const float within = within_p * (1.0f / (float)P_NUM);   // >= 0, O(1)
        const float denom = (float)(nv * (nv - 1));
        const float across = (denom > 0.0f) ? hinge_row / denom : 0.0f; // [0,1]

        const unsigned long long wq = (unsigned long long)__float2uint_rn(within * Q_WITHIN);
        const unsigned long long aq = (unsigned long long)__float2uint_rn(across * Q_ACROSS);
        const unsigned long long contrib =
            (1ull << SH_COUNT) | (wq << SH_WITHIN) | aq;

        const unsigned long long prev = atomicAdd(&g_acc, contrib);

        if ((prev >> SH_COUNT) == (unsigned long long)(N_FLAT - 1)) {
            const unsigned long long tot = prev + contrib;
            const unsigned long long wsum = (tot >> SH_WITHIN) & ((1ull << (SH_COUNT - SH_WITHIN)) - 1ull);
            const unsigned long long asum = tot & ((1ull << SH_WITHIN) - 1ull);
            out[0] = (float)((double)wsum * (1.0 / ((double)Q_WITHIN * N_FLAT)));
            out[1] = (float)((double)asum * (1.0 / ((double)Q_ACROSS * N_FLAT)));
            g_acc = 0ull;   // reset for next graph replay
        }
    }
}

extern "C" void kernel_launch(void* const* d_in, const int* in_sizes, int n_in,
                              void* d_out, int out_size)
{
    const float* preds = (const float*)d_in[0];
    const float* gt    = (const float*)d_in[1];
    float* out = (float*)d_out;
    group_loss_fused<<<N_FLAT, 32>>>(preds, gt, out);
}